// round 1
// baseline (speedup 1.0000x reference)
#include <cuda_runtime.h>
#include <cstddef>

// ButterflyLayer1D: 9 chained batched GEMMs (N=128, K in {128,256}, M=65536 rows).
// Stage types: 0=input proj, 1=down level, 2=middle, 3=up level, 4=final proj.
// Ping-pong activations through two 32MB __device__ scratch buffers.

#define BM 64
#define BN 128
#define BK 32
#define NTHREADS 256

// Scratch: 1024 samples x 64 rows x 128 ch, fp32 (32MB each). Allowed per rules
// (no runtime allocation; __device__ globals are the sanctioned scratch path).
__device__ float g_bufA[1024 * 64 * 128];
__device__ float g_bufB[1024 * 64 * 128];

__global__ __launch_bounds__(NTHREADS)
void stage_kernel(const float* __restrict__ in, const float* __restrict__ w,
                  const float* __restrict__ bias, float* __restrict__ out,
                  int stage, int p0, int p1, int tilesPerGroup, int K)
{
    // As: transposed A tile [k][row] (padded to 68 for store-conflict relief,
    // keeps 16B alignment for float4 reads since 68*4 % 16 == 0).
    __shared__ float As[BK][BM + 4];
    __shared__ float Ws[BK][BN];
    __shared__ const float* sRow0[BM];
    __shared__ const float* sRow1[BM];
    __shared__ float*       sOut[BM];
    __shared__ float        sBias[BN];

    const int tid  = threadIdx.x;
    const int g    = blockIdx.x / tilesPerGroup;   // weight-group index
    const int tile = blockIdx.x % tilesPerGroup;

    // ---- weight/bias base for this group ----
    const float* wg = w;
    const float* bg = bias;
    if (stage == 1)      { wg = w + (size_t)g * 32768; bg = bias + g * 128; } // f[b] = (2,c,c)
    else if (stage == 2) { wg = w + (size_t)g * 16384; bg = bias + g * 128; } // md[k,x] = (c,c), g=k*8+x
    else if (stage == 3) { wg = w + (size_t)g * 32768; bg = bias + g * 128; } // f[2x+j] = (2,c,c), g=2x+j

    // ---- per-row gather/scatter pointers ----
    if (tid < BM) {
        const int t = tile * BM + tid;            // row index within group
        const float* r0 = nullptr; const float* r1 = nullptr; float* o = nullptr;
        if (stage == 0 || stage == 4) {
            r0 = in + (size_t)t * 128;
            o  = out + (size_t)t * 128;
        } else if (stage == 1) {                  // down: out block b=g, K=256 contiguous
            const int n = t / p1, l = t % p1;     // p0=nb_out, p1=Lp_out
            int nb_in = p0 >> 1; if (nb_in == 0) nb_in = 1;
            r0 = in + ((size_t)(n * nb_in + (g >> 1)) * (2 * p1) + 2 * l) * 128;
            r1 = r0 + 128;
            o  = out + ((size_t)(n * p0 + g) * p1 + l) * 128;
        } else if (stage == 2) {                  // middle: g = k*8 + x
            const int n = t;
            const int k = g >> 3, x = g & 7;
            r0 = in  + ((size_t)(n * 8 + k) * 8 + x) * 128;
            o  = out + ((size_t)(n * 8 + x) * 8 + k) * 128;
        } else {                                  // up: g = 2x + j; p0=nbo, p1=Lp_in
            const int n = t / p1, l = t % p1;
            const int x = g >> 1, j = g & 1;
            const int nb_in = p0 * 2;
            r0 = in + ((size_t)(n * nb_in + 2 * x)     * p1 + l) * 128;
            r1 = in + ((size_t)(n * nb_in + 2 * x + 1) * p1 + l) * 128;
            o  = out + ((size_t)(n * p0 + x) * (2 * p1) + 2 * l + j) * 128;
        }
        sRow0[tid] = r0; sRow1[tid] = r1; sOut[tid] = o;
    }
    if (tid < BN) sBias[tid] = (stage == 4) ? 0.0f : bg[tid];
    __syncthreads();

    // ---- micro-tile: 8 rows x 4 cols per thread ----
    float acc[8][4];
    #pragma unroll
    for (int r = 0; r < 8; r++)
        #pragma unroll
        for (int c = 0; c < 4; c++) acc[r][c] = 0.0f;

    const int rowBase = (tid >> 5) * 8;     // 8 row-groups
    const int colBase = (tid & 31) * 4;     // 32 col-groups x 4

    for (int k0 = 0; k0 < K; k0 += BK) {
        // Load A tile (64 rows x 32 k), store transposed. 512 float4 slots.
        #pragma unroll
        for (int i = 0; i < 2; i++) {
            const int s   = tid + i * NTHREADS;
            const int row = s >> 3;
            const int kq  = (s & 7) * 4;
            const int kg  = k0 + kq;
            const float* rp = (kg < 128) ? (sRow0[row] + kg) : (sRow1[row] + kg - 128);
            const float4 v = *(const float4*)rp;
            As[kq + 0][row] = v.x; As[kq + 1][row] = v.y;
            As[kq + 2][row] = v.z; As[kq + 3][row] = v.w;
        }
        // Load W tile (32 k x 128 n). 1024 float4 slots.
        #pragma unroll
        for (int i = 0; i < 4; i++) {
            const int s  = tid + i * NTHREADS;
            const int kk = s >> 5;
            const int dq = (s & 31) * 4;
            *(float4*)&Ws[kk][dq] = *(const float4*)(wg + (size_t)(k0 + kk) * 128 + dq);
        }
        __syncthreads();

        #pragma unroll
        for (int kk = 0; kk < BK; kk++) {
            const float4 a0 = *(const float4*)&As[kk][rowBase];
            const float4 a1 = *(const float4*)&As[kk][rowBase + 4];
            const float4 wv = *(const float4*)&Ws[kk][colBase];
            const float a[8] = {a0.x, a0.y, a0.z, a0.w, a1.x, a1.y, a1.z, a1.w};
            const float wc[4] = {wv.x, wv.y, wv.z, wv.w};
            #pragma unroll
            for (int r = 0; r < 8; r++)
                #pragma unroll
                for (int c = 0; c < 4; c++)
                    acc[r][c] = fmaf(a[r], wc[c], acc[r][c]);
        }
        __syncthreads();
    }

    // ---- epilogue: bias + relu (except final), scatter ----
    const float4 bv = *(const float4*)&sBias[colBase];
    const bool doRelu = (stage != 4);
    #pragma unroll
    for (int r = 0; r < 8; r++) {
        float4 v;
        v.x = acc[r][0] + bv.x; v.y = acc[r][1] + bv.y;
        v.z = acc[r][2] + bv.z; v.w = acc[r][3] + bv.w;
        if (doRelu) {
            v.x = fmaxf(v.x, 0.0f); v.y = fmaxf(v.y, 0.0f);
            v.z = fmaxf(v.z, 0.0f); v.w = fmaxf(v.w, 0.0f);
        }
        *(float4*)(sOut[rowBase + r] + colBase) = v;
    }
}

extern "C" void kernel_launch(void* const* d_in, const int* in_sizes, int n_in,
                              void* d_out, int out_size)
{
    (void)in_sizes; (void)n_in; (void)out_size;
    const float* x  = (const float*)d_in[0];
    const float* xf = (const float*)d_in[1];
    const float* xb = (const float*)d_in[2];
    const float* f1 = (const float*)d_in[3];
    const float* b1 = (const float*)d_in[4];
    const float* f2 = (const float*)d_in[5];
    const float* b2 = (const float*)d_in[6];
    const float* f3 = (const float*)d_in[7];
    const float* b3 = (const float*)d_in[8];
    const float* md = (const float*)d_in[9];
    const float* mb = (const float*)d_in[10];
    const float* f4 = (const float*)d_in[11];
    const float* b4 = (const float*)d_in[12];
    const float* f5 = (const float*)d_in[13];
    const float* b5 = (const float*)d_in[14];
    const float* f6 = (const float*)d_in[15];
    const float* b6 = (const float*)d_in[16];
    const float* kf = (const float*)d_in[17];
    float* out = (float*)d_out;

    float *A = nullptr, *B = nullptr;
    cudaGetSymbolAddress((void**)&A, g_bufA);
    cudaGetSymbolAddress((void**)&B, g_bufB);

    const dim3 grid(1024), block(NTHREADS);
    // stage, p0, p1, tilesPerGroup, K
    stage_kernel<<<grid, block>>>(x, xf, xb, A, 0, 0, 0,  1024, 128);  // proj:   (n,64,128)
    stage_kernel<<<grid, block>>>(A, f1, b1, B, 1, 2, 32, 512,  256);  // down1:  (n,2,32,128)
    stage_kernel<<<grid, block>>>(B, f2, b2, A, 1, 4, 16, 256,  256);  // down2:  (n,4,16,128)
    stage_kernel<<<grid, block>>>(A, f3, b3, B, 1, 8, 8,  128,  256);  // down3:  (n,8,8,128)
    stage_kernel<<<grid, block>>>(B, md, mb, A, 2, 0, 0,  16,   128);  // middle: (n,8,8,128) transposed
    stage_kernel<<<grid, block>>>(A, f4, b4, B, 3, 4, 8,  128,  256);  // up1:    (n,4,16,128)
    stage_kernel<<<grid, block>>>(B, f5, b5, A, 3, 2, 16, 256,  256);  // up2:    (n,2,32,128)
    stage_kernel<<<grid, block>>>(A, f6, b6, B, 3, 1, 32, 512,  256);  // up3:    (n,1,64,128)
    stage_kernel<<<grid, block>>>(B, kf, nullptr, out, 4, 0, 0, 1024, 128); // final
}

// round 3
// speedup vs baseline: 1.5783x; 1.5783x over previous
#include <cuda_runtime.h>
#include <cuda_bf16.h>
#include <cstdint>
#include <cstddef>

// ButterflyLayer1D: 9 chained batched GEMMs (M=65536 rows, N=128, K in {128,256})
// via warp-level mma.sync bf16 (sm_100-legal; tcgen05 requires sm_100a target
// which the harness toolchain does not emit). Split precision: activations and
// weights split to bf16 hi+lo, D = Ah*Wh + Al*Wh + Ah*Wl in fp32 accumulators.

#define SMEM_SWIZ(off) ((off) ^ (((off) >> 3) & 0x70))

__device__ __forceinline__ uint32_t smem_u32(const void* p) {
    uint32_t a;
    asm("{ .reg .u64 t; cvta.to.shared.u64 t, %1; cvt.u32.u64 %0, t; }" : "=r"(a) : "l"(p));
    return a;
}

__device__ __forceinline__ void ldsm_x4(uint32_t* r, uint32_t a) {
    asm volatile("ldmatrix.sync.aligned.m8n8.x4.shared.b16 {%0,%1,%2,%3}, [%4];"
        : "=r"(r[0]), "=r"(r[1]), "=r"(r[2]), "=r"(r[3]) : "r"(a));
}

__device__ __forceinline__ void mma_bf16(float* d, const uint32_t* a, const uint32_t* b) {
    asm volatile(
        "mma.sync.aligned.m16n8k16.row.col.f32.bf16.bf16.f32 "
        "{%0,%1,%2,%3}, {%4,%5,%6,%7}, {%8,%9}, {%0,%1,%2,%3};"
        : "+f"(d[0]), "+f"(d[1]), "+f"(d[2]), "+f"(d[3])
        : "r"(a[0]), "r"(a[1]), "r"(a[2]), "r"(a[3]), "r"(b[0]), "r"(b[1]));
}

__device__ __forceinline__ unsigned packbf(__nv_bfloat16 a, __nv_bfloat16 b) {
    return ((unsigned)__bfloat16_as_ushort(b) << 16) | (unsigned)__bfloat16_as_ushort(a);
}

// ---------------- global scratch ----------------
__device__ float g_bufA[1024 * 64 * 128];
__device__ float g_bufB[1024 * 64 * 128];
#define WTOTAL 1998848
__device__ unsigned short g_whi_raw[WTOTAL];
__device__ unsigned short g_wlo_raw[WTOTAL];

// ---------------- weight prep: transpose + split to bf16 hi/lo ----------------
__global__ void prep_weights(const float* __restrict__ xf, const float* __restrict__ f1,
                             const float* __restrict__ f2, const float* __restrict__ f3,
                             const float* __restrict__ md, const float* __restrict__ f4,
                             const float* __restrict__ f5, const float* __restrict__ f6,
                             const float* __restrict__ kf)
{
    const int e = blockIdx.x * blockDim.x + threadIdx.x;
    if (e >= WTOTAL) return;
    const int off[10] = {0, 16384, 81920, 212992, 475136, 1523712, 1785856, 1916928, 1982464, WTOTAL};
    int t = 0;
    #pragma unroll
    for (int i = 1; i < 9; i++) if (e >= off[i]) t = i;
    const int K = (t == 0 || t == 4 || t == 8) ? 128 : 256;
    const float* src;
    switch (t) {
        case 0: src = xf; break; case 1: src = f1; break; case 2: src = f2; break;
        case 3: src = f3; break; case 4: src = md; break; case 5: src = f4; break;
        case 6: src = f5; break; case 7: src = f6; break; default: src = kf; break;
    }
    const int local = e - off[t];
    const int per = K * 128;
    const int g = local / per, rem = local % per;
    const int kk = rem >> 7, n = rem & 127;       // src [g][kk][n]
    const float v = src[local];
    const __nv_bfloat16 h = __float2bfloat16(v);
    const float lr = v - __bfloat162float(h);
    const int di = off[t] + g * per + n * K + kk; // dst [g][n][kk] (transposed)
    g_whi_raw[di] = __bfloat16_as_ushort(h);
    g_wlo_raw[di] = __bfloat16_as_ushort(__float2bfloat16(lr));
}

// ---------------- stage kernel (mma.sync bf16) ----------------
// CTA tile M=128 x N=128, K chunks of 64. SMEM tiles: 128 rows x 64 bf16
// (128B/row), XOR-swizzled for conflict-free ldmatrix.
#define DYN_SMEM 65536

__global__ __launch_bounds__(256, 2)
void stage_mma(const float* __restrict__ in, const __nv_bfloat16* __restrict__ wh,
               const __nv_bfloat16* __restrict__ wl, const float* __restrict__ bias,
               float* __restrict__ out, int stage, int p0, int p1, int tpg, int K)
{
    __shared__ const float* sRow0[128];
    __shared__ const float* sRow1[128];
    __shared__ float*       sOut[128];
    __shared__ float        sBias[128];
    extern __shared__ __align__(16) char dyn[];
    char* Ah = dyn;           char* Al = dyn + 16384;
    char* Wh = dyn + 32768;   char* Wl = dyn + 49152;

    const int tid = threadIdx.x;
    const int lane = tid & 31, wid = tid >> 5;
    const int g    = blockIdx.x / tpg;
    const int tile = blockIdx.x % tpg;

    const size_t gstride = (size_t)K * 128;
    const __nv_bfloat16* whg = wh + (size_t)g * gstride;
    const __nv_bfloat16* wlg = wl + (size_t)g * gstride;

    // ---- per-row gather/scatter pointers (proven R1 indexing) ----
    if (tid < 128) {
        const int t = tile * 128 + tid;
        const float* r0 = nullptr; const float* r1 = nullptr; float* o = nullptr;
        if (stage == 0 || stage == 4) {
            r0 = in + (size_t)t * 128;
            o  = out + (size_t)t * 128;
        } else if (stage == 1) {                  // down
            const int n = t / p1, l = t % p1;
            int nb_in = p0 >> 1; if (nb_in == 0) nb_in = 1;
            r0 = in + ((size_t)(n * nb_in + (g >> 1)) * (2 * p1) + 2 * l) * 128;
            r1 = r0 + 128;
            o  = out + ((size_t)(n * p0 + g) * p1 + l) * 128;
        } else if (stage == 2) {                  // middle: g = k*8 + x
            const int n = t;
            const int k = g >> 3, x = g & 7;
            r0 = in  + ((size_t)(n * 8 + k) * 8 + x) * 128;
            o  = out + ((size_t)(n * 8 + x) * 8 + k) * 128;
        } else {                                  // up: g = 2x + j
            const int n = t / p1, l = t % p1;
            const int x = g >> 1, j = g & 1;
            const int nb_in = p0 * 2;
            r0 = in + ((size_t)(n * nb_in + 2 * x)     * p1 + l) * 128;
            r1 = in + ((size_t)(n * nb_in + 2 * x + 1) * p1 + l) * 128;
            o  = out + ((size_t)(n * p0 + x) * (2 * p1) + 2 * l + j) * 128;
        }
        sRow0[tid] = r0; sRow1[tid] = r1; sOut[tid] = o;
        const float* bg = bias ? (bias + ((stage >= 1 && stage <= 3) ? g * 128 : 0)) : nullptr;
        sBias[tid] = bg ? bg[tid] : 0.0f;
    }
    __syncthreads();

    const uint32_t AhU = smem_u32(Ah), AlU = smem_u32(Al);
    const uint32_t WhU = smem_u32(Wh), WlU = smem_u32(Wl);

    // ---- warp tiling: 4x2 warps, each m32 x n64 ----
    const int warpM = wid >> 1, warpN = wid & 1;

    int offA[2], swA[2];
    #pragma unroll
    for (int mt = 0; mt < 2; mt++) {
        const int r = warpM * 32 + mt * 16 + ((lane & 8) ? 8 : 0) + (lane & 7);
        offA[mt] = r * 128; swA[mt] = (r & 7) << 4;
    }
    const int kaddA = (lane & 16) ? 16 : 0;
    int offB[4], swB[4];
    #pragma unroll
    for (int nt2 = 0; nt2 < 4; nt2++) {
        const int n = warpN * 64 + nt2 * 16 + ((lane & 16) ? 8 : 0) + (lane & 7);
        offB[nt2] = n * 128; swB[nt2] = (n & 7) << 4;
    }
    const int kaddB = (lane & 8) ? 16 : 0;

    float c[2][8][4];
    #pragma unroll
    for (int mt = 0; mt < 2; mt++)
        #pragma unroll
        for (int nt = 0; nt < 8; nt++)
            #pragma unroll
            for (int i = 0; i < 4; i++) c[mt][nt][i] = 0.0f;

    const int nk = K >> 6;
    for (int ch = 0; ch < nk; ch++) {
        const int k0 = ch << 6;
        // ---- A tile: 128 rows x 64 fp32 -> hi/lo bf16 (swizzled) ----
        #pragma unroll
        for (int i = 0; i < 8; i++) {
            const int s = tid + (i << 8);
            const int row = s >> 4, q = s & 15;
            const int k = k0 + (q << 2);
            const float* rp = (k < 128) ? (sRow0[row] + k) : (sRow1[row] + (k - 128));
            const float4 v = *(const float4*)rp;
            const __nv_bfloat16 hx = __float2bfloat16(v.x), hy = __float2bfloat16(v.y);
            const __nv_bfloat16 hz = __float2bfloat16(v.z), hw = __float2bfloat16(v.w);
            const __nv_bfloat16 lx = __float2bfloat16(v.x - __bfloat162float(hx));
            const __nv_bfloat16 ly = __float2bfloat16(v.y - __bfloat162float(hy));
            const __nv_bfloat16 lz = __float2bfloat16(v.z - __bfloat162float(hz));
            const __nv_bfloat16 lw = __float2bfloat16(v.w - __bfloat162float(hw));
            const unsigned sw = SMEM_SWIZ((unsigned)(row * 128 + q * 8));
            *(uint2*)(Ah + sw) = make_uint2(packbf(hx, hy), packbf(hz, hw));
            *(uint2*)(Al + sw) = make_uint2(packbf(lx, ly), packbf(lz, lw));
        }
        // ---- W tiles: 128 n-rows x 64 bf16 (hi + lo), swizzled ----
        #pragma unroll
        for (int i = 0; i < 4; i++) {
            const int s = tid + (i << 8);
            const int n = s >> 3, c16 = s & 7;
            const size_t so = (size_t)n * K + k0 + (c16 << 3);
            const float4 hv = *(const float4*)(whg + so);
            const float4 lv = *(const float4*)(wlg + so);
            const unsigned sw = SMEM_SWIZ((unsigned)(n * 128 + (c16 << 4)));
            *(float4*)(Wh + sw) = hv;
            *(float4*)(Wl + sw) = lv;
        }
        __syncthreads();

        #pragma unroll
        for (int ks = 0; ks < 4; ks++) {
            const int kb = ks * 32;               // 16 bf16 = 32 bytes
            uint32_t ah[2][4], al[2][4];
            #pragma unroll
            for (int mt = 0; mt < 2; mt++) {
                ldsm_x4(ah[mt], AhU + offA[mt] + ((kb + kaddA) ^ swA[mt]));
                ldsm_x4(al[mt], AlU + offA[mt] + ((kb + kaddA) ^ swA[mt]));
            }
            #pragma unroll
            for (int nt2 = 0; nt2 < 4; nt2++) {
                uint32_t bh[4], bl[4];
                ldsm_x4(bh, WhU + offB[nt2] + ((kb + kaddB) ^ swB[nt2]));
                ldsm_x4(bl, WlU + offB[nt2] + ((kb + kaddB) ^ swB[nt2]));
                #pragma unroll
                for (int mt = 0; mt < 2; mt++) {
                    #pragma unroll
                    for (int h = 0; h < 2; h++) {
                        float* cc = c[mt][nt2 * 2 + h];
                        mma_bf16(cc, ah[mt], bh + h * 2);
                        mma_bf16(cc, al[mt], bh + h * 2);
                        mma_bf16(cc, ah[mt], bl + h * 2);
                    }
                }
            }
        }
        __syncthreads();
    }

    // ---- epilogue: bias + relu (except final), scatter ----
    const bool doRelu = (stage != 4);
    #pragma unroll
    for (int mt = 0; mt < 2; mt++) {
        const int rbase = warpM * 32 + mt * 16 + (lane >> 2);
        #pragma unroll
        for (int h = 0; h < 2; h++) {             // rows rbase, rbase+8
            float* op = sOut[rbase + h * 8];
            #pragma unroll
            for (int nt = 0; nt < 8; nt++) {
                const int col = warpN * 64 + nt * 8 + 2 * (lane & 3);
                float v0 = c[mt][nt][h * 2 + 0] + sBias[col];
                float v1 = c[mt][nt][h * 2 + 1] + sBias[col + 1];
                if (doRelu) { v0 = fmaxf(v0, 0.0f); v1 = fmaxf(v1, 0.0f); }
                float2 v; v.x = v0; v.y = v1;
                *(float2*)(op + col) = v;
            }
        }
    }
}

// ---------------- launch ----------------
extern "C" void kernel_launch(void* const* d_in, const int* in_sizes, int n_in,
                              void* d_out, int out_size)
{
    (void)in_sizes; (void)n_in; (void)out_size;
    const float* x  = (const float*)d_in[0];
    const float* xf = (const float*)d_in[1];
    const float* xb = (const float*)d_in[2];
    const float* f1 = (const float*)d_in[3];
    const float* b1 = (const float*)d_in[4];
    const float* f2 = (const float*)d_in[5];
    const float* b2 = (const float*)d_in[6];
    const float* f3 = (const float*)d_in[7];
    const float* b3 = (const float*)d_in[8];
    const float* md = (const float*)d_in[9];
    const float* mb = (const float*)d_in[10];
    const float* f4 = (const float*)d_in[11];
    const float* b4 = (const float*)d_in[12];
    const float* f5 = (const float*)d_in[13];
    const float* b5 = (const float*)d_in[14];
    const float* f6 = (const float*)d_in[15];
    const float* b6 = (const float*)d_in[16];
    const float* kf = (const float*)d_in[17];
    float* out = (float*)d_out;

    float *A = nullptr, *B = nullptr;
    unsigned short *whiR = nullptr, *wloR = nullptr;
    cudaGetSymbolAddress((void**)&A, g_bufA);
    cudaGetSymbolAddress((void**)&B, g_bufB);
    cudaGetSymbolAddress((void**)&whiR, g_whi_raw);
    cudaGetSymbolAddress((void**)&wloR, g_wlo_raw);
    const __nv_bfloat16* whi = (const __nv_bfloat16*)whiR;
    const __nv_bfloat16* wlo = (const __nv_bfloat16*)wloR;

    cudaFuncSetAttribute(stage_mma, cudaFuncAttributeMaxDynamicSharedMemorySize, DYN_SMEM);

    prep_weights<<<(WTOTAL + 255) / 256, 256>>>(xf, f1, f2, f3, md, f4, f5, f6, kf);

    const int Oxf = 0, Of1 = 16384, Of2 = 81920, Of3 = 212992, Omd = 475136,
              Of4 = 1523712, Of5 = 1785856, Of6 = 1916928, Okf = 1982464;

    const dim3 grid(512), block(256);
    // (in, whi, wlo, bias, out, stage, p0, p1, tilesPerGroup, K)
    stage_mma<<<grid, block, DYN_SMEM>>>(x, whi + Oxf, wlo + Oxf, xb, A, 0, 0, 0,  512, 128);
    stage_mma<<<grid, block, DYN_SMEM>>>(A, whi + Of1, wlo + Of1, b1, B, 1, 2, 32, 256, 256);
    stage_mma<<<grid, block, DYN_SMEM>>>(B, whi + Of2, wlo + Of2, b2, A, 1, 4, 16, 128, 256);
    stage_mma<<<grid, block, DYN_SMEM>>>(A, whi + Of3, wlo + Of3, b3, B, 1, 8, 8,  64,  256);
    stage_mma<<<grid, block, DYN_SMEM>>>(B, whi + Omd, wlo + Omd, mb, A, 2, 0, 0,  8,   128);
    stage_mma<<<grid, block, DYN_SMEM>>>(A, whi + Of4, wlo + Of4, b4, B, 3, 4, 8,  64,  256);
    stage_mma<<<grid, block, DYN_SMEM>>>(B, whi + Of5, wlo + Of5, b5, A, 3, 2, 16, 128, 256);
    stage_mma<<<grid, block, DYN_SMEM>>>(A, whi + Of6, wlo + Of6, b6, B, 3, 1, 32, 256, 256);
    stage_mma<<<grid, block, DYN_SMEM>>>(B, whi + Okf, wlo + Okf, nullptr, out, 4, 0, 0, 512, 128);
}